// round 12
// baseline (speedup 1.0000x reference)
#include <cuda_runtime.h>
#include <math.h>

#define Bn 16
#define Cn 256
#define Ln 64
#define Nn 8192
#define Hn 8
#define HC 32          // C / H
#define Mn 12
#define KSPLIT 4
#define CnLn (Cn * Ln)
#define SQRT32 5.656854249492381f
#define RS_BN 0.9999950000374997f   // 1/sqrt(1 + 1e-5)
#define PI_F 3.14159265358979323846f

// ---------------- scratch (device globals; no allocation) ----------------
__device__ float g_qkvp[KSPLIT][Bn * 3 * Cn * Ln];  // K-split partial sums (no bias)
__device__ float g_xncol[Bn * Cn];                  // xn_pre per (b,c) (const along n)

// packed f32x2 helpers (Blackwell): 2 fp32 FMAs per instruction, IEEE-exact
__device__ __forceinline__ void fma2(unsigned long long& d,
                                     unsigned long long a,
                                     unsigned long long b) {
    asm("fma.rn.f32x2 %0, %1, %2, %0;" : "+l"(d) : "l"(a), "l"(b));
}
__device__ __forceinline__ unsigned long long dup2(float w) {
    unsigned long long r;
    asm("mov.b64 %0, {%1, %1};" : "=l"(r) : "f"(w));
    return r;
}
__device__ __forceinline__ float2 unpk(unsigned long long a) {
    float lo, hi;
    asm("mov.b64 {%0, %1}, %2;" : "=f"(lo), "=f"(hi) : "l"(a));
    return make_float2(lo, hi);
}

// ---------------- kernel 1: qkv partials (K-split x4) ----------------
// grid (12, 16, 4). block 256, 4r x 4c f32x2 micro-tile.
// All 8 memory ops per j4 issued up-front for MLP before the FMA burst.
__global__ void __launch_bounds__(256) k_qkv(const float* __restrict__ xt,
                                             const float* __restrict__ enc_w)
{
    __shared__ ulonglong2 xs4[64 * 16];      // 64 j-rows x 64 cols = 16KB
    const int b  = blockIdx.y;
    const int rt = blockIdx.x;
    const int kq = blockIdx.z;
    const ulonglong2* xb4 = (const ulonglong2*)(xt + b * Cn * Ln);

    for (int i = threadIdx.x; i < 1024; i += 256) xs4[i] = xb4[kq * 1024 + i];

    const int rg = threadIdx.x >> 4;
    const int cg = threadIdx.x & 15;
    const int row0 = rt * 64 + rg * 4;

    const float4* w0p = (const float4*)(enc_w + (row0 + 0) * Cn + kq * 64);
    const float4* w1p = (const float4*)(enc_w + (row0 + 1) * Cn + kq * 64);
    const float4* w2p = (const float4*)(enc_w + (row0 + 2) * Cn + kq * 64);
    const float4* w3p = (const float4*)(enc_w + (row0 + 3) * Cn + kq * 64);

    unsigned long long acc[4][2];
    #pragma unroll
    for (int r = 0; r < 4; r++) { acc[r][0] = 0ull; acc[r][1] = 0ull; }

    __syncthreads();
    #pragma unroll 4
    for (int j4 = 0; j4 < 16; j4++) {
        // batch all memory ops first (4 LDG + 4 LDS in flight together)
        const float4 w0 = w0p[j4], w1 = w1p[j4], w2 = w2p[j4], w3 = w3p[j4];
        const ulonglong2 xv0 = xs4[(j4 * 4 + 0) * 16 + cg];
        const ulonglong2 xv1 = xs4[(j4 * 4 + 1) * 16 + cg];
        const ulonglong2 xv2 = xs4[(j4 * 4 + 2) * 16 + cg];
        const ulonglong2 xv3 = xs4[(j4 * 4 + 3) * 16 + cg];

        unsigned long long d;
        d = dup2(w0.x); fma2(acc[0][0], d, xv0.x); fma2(acc[0][1], d, xv0.y);
        d = dup2(w0.y); fma2(acc[0][0], d, xv1.x); fma2(acc[0][1], d, xv1.y);
        d = dup2(w0.z); fma2(acc[0][0], d, xv2.x); fma2(acc[0][1], d, xv2.y);
        d = dup2(w0.w); fma2(acc[0][0], d, xv3.x); fma2(acc[0][1], d, xv3.y);
        d = dup2(w1.x); fma2(acc[1][0], d, xv0.x); fma2(acc[1][1], d, xv0.y);
        d = dup2(w1.y); fma2(acc[1][0], d, xv1.x); fma2(acc[1][1], d, xv1.y);
        d = dup2(w1.z); fma2(acc[1][0], d, xv2.x); fma2(acc[1][1], d, xv2.y);
        d = dup2(w1.w); fma2(acc[1][0], d, xv3.x); fma2(acc[1][1], d, xv3.y);
        d = dup2(w2.x); fma2(acc[2][0], d, xv0.x); fma2(acc[2][1], d, xv0.y);
        d = dup2(w2.y); fma2(acc[2][0], d, xv1.x); fma2(acc[2][1], d, xv1.y);
        d = dup2(w2.z); fma2(acc[2][0], d, xv2.x); fma2(acc[2][1], d, xv2.y);
        d = dup2(w2.w); fma2(acc[2][0], d, xv3.x); fma2(acc[2][1], d, xv3.y);
        d = dup2(w3.x); fma2(acc[3][0], d, xv0.x); fma2(acc[3][1], d, xv0.y);
        d = dup2(w3.y); fma2(acc[3][0], d, xv1.x); fma2(acc[3][1], d, xv1.y);
        d = dup2(w3.z); fma2(acc[3][0], d, xv2.x); fma2(acc[3][1], d, xv2.y);
        d = dup2(w3.w); fma2(acc[3][0], d, xv3.x); fma2(acc[3][1], d, xv3.y);
    }

    #pragma unroll
    for (int r = 0; r < 4; r++) {
        const int o = row0 + r;
        const float2 p0 = unpk(acc[r][0]);
        const float2 p1 = unpk(acc[r][1]);
        float4 res = make_float4(p0.x, p0.y, p1.x, p1.y);
        ((float4*)(g_qkvp[kq] + (size_t)b * 3 * CnLn + o * Ln))[cg] = res;
    }
}

// ---------------- kernel 2: fused enc-attn + fourier + dec-attn ----------------
// grid (H, B), block 512 (16 warps). Warp w covers l = w*4 + (lane>>3); g = lane&7.
// Score pass: g splits 64 s into 8 each. Weighted-V/fourier: g splits 32 ch into 4 each.
__global__ void __launch_bounds__(512) k_fused(const float* __restrict__ xt,
                                               const float* __restrict__ enc_b,
                                               const float* __restrict__ weights,
                                               const float* __restrict__ mask_token,
                                               const float* __restrict__ dec_w,
                                               const float* __restrict__ dec_b)
{
    __shared__ float qs[64 * 33];       // Q[s][c]
    __shared__ float ks[64 * 33];       // K[s][c]
    __shared__ float vs[64 * 33];       // V[s][c]
    __shared__ float es[HC * 65];       // encoder-out slice [c][l]
    __shared__ float ws[HC * 24];
    __shared__ float mask_s[Cn];
    __shared__ float q_s[HC];
    __shared__ float p_s[Ln];
    // total 38144 B < 48KB

    const int h = blockIdx.x, b = blockIdx.y;
    const int t = threadIdx.x;
    const int lane = t & 31;
    const int l = (t >> 5) * 4 + (lane >> 3);
    const int g = lane & 7;

    const size_t off = (size_t)b * 3 * CnLn + (h * HC) * Ln;
    const float* a0 = g_qkvp[0] + off;
    const float* a1 = g_qkvp[1] + off;
    const float* a2 = g_qkvp[2] + off;
    const float* a3 = g_qkvp[3] + off;

    for (int i = t; i < 2048; i += 512) {
        const int cc = i >> 6, s = i & 63;
        const int idx = cc * Ln + s;
        const float bq = enc_b[h * HC + cc];
        const float bk = enc_b[Cn + h * HC + cc];
        const float bv = enc_b[2 * Cn + h * HC + cc];
        qs[s * 33 + cc] = a0[idx] + a1[idx] + a2[idx] + a3[idx] + bq;
        ks[s * 33 + cc] = a0[CnLn + idx] + a1[CnLn + idx] + a2[CnLn + idx] + a3[CnLn + idx] + bk;
        vs[s * 33 + cc] = a0[2*CnLn + idx] + a1[2*CnLn + idx] + a2[2*CnLn + idx] + a3[2*CnLn + idx] + bv;
    }
    if (t < Cn) mask_s[t] = mask_token[t];
    for (int i = t; i < HC * 24; i += 512) {
        int cc = i / 24, m = i - cc * 24;
        ws[i] = weights[(h * HC + cc) * 24 + m];
    }
    __syncthreads();

    float q[HC];
    #pragma unroll
    for (int cc = 0; cc < HC; cc++) q[cc] = qs[l * 33 + cc];

    // ---- scores: this thread handles s = g, g+8, ..., g+56 ----
    float dloc[8];
    float mx = -1e30f;
    #pragma unroll
    for (int i = 0; i < 8; i++) {
        const int s = g + i * 8;
        float d = 0.f;
        #pragma unroll
        for (int cc = 0; cc < HC; cc++) d = fmaf(q[cc], ks[s * 33 + cc], d);
        d *= SQRT32;
        dloc[i] = d;
        mx = fmaxf(mx, d);
    }
    mx = fmaxf(mx, __shfl_xor_sync(0xffffffffu, mx, 1));
    mx = fmaxf(mx, __shfl_xor_sync(0xffffffffu, mx, 2));
    mx = fmaxf(mx, __shfl_xor_sync(0xffffffffu, mx, 4));

    float sum = 0.f;
    #pragma unroll
    for (int i = 0; i < 8; i++) {
        const float e = __expf(dloc[i] - mx);
        dloc[i] = e;
        sum += e;
    }
    sum += __shfl_xor_sync(0xffffffffu, sum, 1);
    sum += __shfl_xor_sync(0xffffffffu, sum, 2);
    sum += __shfl_xor_sync(0xffffffffu, sum, 4);
    const float inv = 1.f / sum;

    // ---- weighted V (channels g*4..g*4+3); exps exchanged via shfl ----
    float acc[4];
    #pragma unroll
    for (int j = 0; j < 4; j++) acc[j] = 0.f;
    #pragma unroll 16
    for (int s = 0; s < 64; s++) {
        const int src = (lane & 24) | (s & 7);
        const float p = __shfl_sync(0xffffffffu, dloc[s >> 3], src);
        #pragma unroll
        for (int j = 0; j < 4; j++) acc[j] = fmaf(p, vs[s * 33 + g * 4 + j], acc[j]);
    }

    // ---- fourier + residual -> es ----
    const float* xrow = xt + (size_t)b * Cn * Ln + (h * HC) * Ln;
    #pragma unroll
    for (int j = 0; j < 4; j++) {
        const int cc = g * 4 + j;
        const float a = acc[j] * inv;
        const float phi = a * (PI_F / (float)Mn);
        float s1, c1;
        __sincosf(phi, &s1, &c1);
        const float* w = ws + cc * 24;
        float fv = w[Mn];
        float sm = s1, cm = c1;
        #pragma unroll
        for (int m = 1; m < Mn; m++) {
            fv = fmaf(w[m], sm, fv);
            fv = fmaf(w[Mn + m], cm, fv);
            float sn = sm * c1 + cm * s1;
            cm = cm * c1 - sm * s1;
            sm = sn;
        }
        es[cc * 65 + l] = fv + xrow[cc * Ln + l];
    }

    // ---- decoder q: 16 threads per output row ----
    {
        const int c = t >> 4, part = t & 15;
        const int row = h * HC + c;
        const float4* wp = (const float4*)(dec_w + row * Cn) + part * 4;
        const float4* mp = (const float4*)(mask_s) + part * 4;
        float a4 = 0.f;
        #pragma unroll
        for (int i = 0; i < 4; i++) {
            float4 w4 = wp[i], m4 = mp[i];
            a4 = fmaf(w4.x, m4.x, a4); a4 = fmaf(w4.y, m4.y, a4);
            a4 = fmaf(w4.z, m4.z, a4); a4 = fmaf(w4.w, m4.w, a4);
        }
        a4 += __shfl_xor_sync(0xffffffffu, a4, 1);
        a4 += __shfl_xor_sync(0xffffffffu, a4, 2);
        a4 += __shfl_xor_sync(0xffffffffu, a4, 4);
        a4 += __shfl_xor_sync(0xffffffffu, a4, 8);
        if (part == 0) q_s[c] = a4 + dec_b[row];
    }
    __syncthreads();

    if (t < Ln) {
        float d = 0.f;
        #pragma unroll
        for (int cc = 0; cc < HC; cc++) d = fmaf(q_s[cc], es[cc * 65 + t], d);
        p_s[t] = d * SQRT32;
    }
    __syncthreads();

    if (t < 32) {
        float v0 = p_s[t], v1 = p_s[t + 32];
        float m = fmaxf(v0, v1);
        #pragma unroll
        for (int off2 = 16; off2; off2 >>= 1) m = fmaxf(m, __shfl_xor_sync(0xffffffffu, m, off2));
        float e0 = __expf(v0 - m), e1 = __expf(v1 - m);
        float s = e0 + e1;
        #pragma unroll
        for (int off2 = 16; off2; off2 >>= 1) s += __shfl_xor_sync(0xffffffffu, s, off2);
        float pin = 1.f / s;
        p_s[t]      = e0 * pin;
        p_s[t + 32] = e1 * pin;
    }
    __syncthreads();

    if (t < HC) {
        float a5 = 0.f;
        #pragma unroll
        for (int ll = 0; ll < Ln; ll++) a5 = fmaf(p_s[ll], es[t * 65 + ll], a5);
        g_xncol[b * Cn + h * HC + t] = a5 + mask_s[h * HC + t];
    }
}

// ---------------- kernel 3: broadcast xn + (head MLP + broadcast y) ----------------
__global__ void __launch_bounds__(256) k_bcast(float4* __restrict__ out4,
                                               const float* __restrict__ fc1_w,
                                               const float* __restrict__ fc1_g,
                                               const float* __restrict__ fc1_b,
                                               const float* __restrict__ fc2_w,
                                               const float* __restrict__ fc2_g,
                                               const float* __restrict__ fc2_b)
{
    const int t = threadIdx.x;
    if (blockIdx.x < 2048) {
        const int row = blockIdx.x * 2 + (t >> 7);      // b*Cn + c
        const int lane = t & 127;
        const float v = g_xncol[row];
        const float4 v4 = make_float4(v, v, v, v);
        float4* p = out4 + (size_t)row * 2048 + lane;
        #pragma unroll
        for (int i = 0; i < 16; i++) p[i * 128] = v4;
    } else {
        __shared__ float xn_s[Cn];
        __shared__ float y1_s[Cn];
        __shared__ float y2_s[3];
        const int b = blockIdx.x - 2048;

        xn_s[t] = g_xncol[b * Cn + t];
        __syncthreads();

        {
            float acc = 0.f;
            const float4* wr = (const float4*)(fc1_w + t * Cn);
            const float4* xr = (const float4*)xn_s;
            #pragma unroll 8
            for (int i = 0; i < 64; i++) {
                float4 w4 = wr[i], x4 = xr[i];
                acc = fmaf(w4.x, x4.x, acc); acc = fmaf(w4.y, x4.y, acc);
                acc = fmaf(w4.z, x4.z, acc); acc = fmaf(w4.w, x4.w, acc);
            }
            float y = fc1_g[t] * acc * RS_BN + fc1_b[t];
            y1_s[t] = (y >= 0.f) ? y : 0.2f * y;
        }
        __syncthreads();

        {
            const int w = t >> 5, lane = t & 31;
            if (w < 3) {
                const float4* wr = (const float4*)(fc2_w + w * Cn) + lane * 2;
                const float4* yr = (const float4*)y1_s + lane * 2;
                float acc = 0.f;
                #pragma unroll
                for (int i = 0; i < 2; i++) {
                    float4 w4 = wr[i], y4 = yr[i];
                    acc = fmaf(w4.x, y4.x, acc); acc = fmaf(w4.y, y4.y, acc);
                    acc = fmaf(w4.z, y4.z, acc); acc = fmaf(w4.w, y4.w, acc);
                }
                #pragma unroll
                for (int off = 16; off; off >>= 1) acc += __shfl_xor_sync(0xffffffffu, acc, off);
                if (lane == 0) {
                    float y = fc2_g[w] * acc * RS_BN + fc2_b[w];
                    y2_s[w] = (y >= 0.f) ? y : 0.2f * y;
                }
            }
        }
        __syncthreads();

        const float y0 = y2_s[0], y1 = y2_s[1], y2v = y2_s[2];
        float4 var[3];
        var[0] = make_float4(y0, y1, y2v, y0);
        var[1] = make_float4(y1, y2v, y0, y1);
        var[2] = make_float4(y2v, y0, y1, y2v);
        float4* p = out4 + (size_t)(Bn * Cn * Nn) / 4 + (size_t)b * 6144;
        for (int i = t; i < 6144; i += 256) p[i] = var[i % 3];
    }
}

// ---------------- launch ----------------
extern "C" void kernel_launch(void* const* d_in, const int* in_sizes, int n_in,
                              void* d_out, int out_size)
{
    const float* xt        = (const float*)d_in[0];
    /* xn = d_in[1] never read: fully-masked path */
    const float* weights   = (const float*)d_in[2];
    const float* mask_tok  = (const float*)d_in[3];
    const float* enc_w     = (const float*)d_in[4];
    const float* enc_b     = (const float*)d_in[5];
    const float* dec_w     = (const float*)d_in[6];
    const float* dec_b     = (const float*)d_in[7];
    const float* fc1_w     = (const float*)d_in[8];
    const float* fc1_g     = (const float*)d_in[9];
    const float* fc1_b     = (const float*)d_in[10];
    const float* fc2_w     = (const float*)d_in[11];
    const float* fc2_g     = (const float*)d_in[12];
    const float* fc2_b     = (const float*)d_in[13];
    float* out = (float*)d_out;

    k_qkv  <<<dim3(12, Bn, KSPLIT), 256>>>(xt, enc_w);
    k_fused<<<dim3(Hn, Bn), 512>>>(xt, enc_b, weights, mask_tok, dec_w, dec_b);
    k_bcast<<<2064, 256>>>((float4*)out, fc1_w, fc1_g, fc1_b, fc2_w, fc2_g, fc2_b);
}

// round 13
// speedup vs baseline: 1.0639x; 1.0639x over previous
#include <cuda_runtime.h>
#include <math.h>

#define Bn 16
#define Cn 256
#define Ln 64
#define Nn 8192
#define Hn 8
#define HC 32          // C / H
#define Mn 12
#define SQRT32 5.656854249492381f
#define RS_BN 0.9999950000374997f   // 1/sqrt(1 + 1e-5)
#define PI_F 3.14159265358979323846f

// ---------------- scratch (device globals; no allocation) ----------------
__device__ float g_xncol[Bn * Cn];          // xn_pre per (b,c) (const along n)

// packed f32x2 helpers (Blackwell): 2 fp32 FMAs per instruction, IEEE-exact
__device__ __forceinline__ void fma2(unsigned long long& d,
                                     unsigned long long a,
                                     unsigned long long b) {
    asm("fma.rn.f32x2 %0, %1, %2, %0;" : "+l"(d) : "l"(a), "l"(b));
}
__device__ __forceinline__ unsigned long long dup2(float w) {
    unsigned long long r;
    asm("mov.b64 %0, {%1, %1};" : "=l"(r) : "f"(w));
    return r;
}
__device__ __forceinline__ float2 unpk(unsigned long long a) {
    float lo, hi;
    asm("mov.b64 {%0, %1}, %2;" : "=f"(lo), "=f"(hi) : "l"(a));
    return make_float2(lo, hi);
}

// dynamic smem layout (bytes)
#define OFF_XS   0                       // ulonglong2[256*16]  xt[b] as [j=256][s=64]
#define OFF_QS   65536                   // float[64*33]  Q[s][c]
#define OFF_KS   (OFF_QS + 8448)
#define OFF_VS   (OFF_KS + 8448)
#define OFF_ES   (OFF_VS + 8448)         // float[32*65]  encoder-out [c][l]
#define OFF_WS   (OFF_ES + 8320)         // float[32*24]
#define OFF_MASK (OFF_WS + 3072)         // float[256]
#define OFF_QD   (OFF_MASK + 1024)       // float[32]
#define OFF_PS   (OFF_QD + 128)          // float[64]
#define SMEM_TOTAL (OFF_PS + 256)        // 103680 B

// ---------------- kernel 1: QKV GEMM + enc-attn + fourier + dec-attn ----------------
// grid (H, B), block 512. GEMM: rg=t>>4 (channel 0..31), cg=t&15 (4 L-cols);
// each thread computes the Q, K and V row for its channel over its 4 cols.
// Attention: warp w covers l = w*4 + (lane>>3); g = lane&7.
__global__ void __launch_bounds__(512) k_fused(const float* __restrict__ xt,
                                               const float* __restrict__ enc_w,
                                               const float* __restrict__ enc_b,
                                               const float* __restrict__ weights,
                                               const float* __restrict__ mask_token,
                                               const float* __restrict__ dec_w,
                                               const float* __restrict__ dec_b)
{
    extern __shared__ char smem[];
    ulonglong2* xs4   = (ulonglong2*)(smem + OFF_XS);
    float* qs         = (float*)(smem + OFF_QS);
    float* ks         = (float*)(smem + OFF_KS);
    float* vs         = (float*)(smem + OFF_VS);
    float* es         = (float*)(smem + OFF_ES);
    float* ws         = (float*)(smem + OFF_WS);
    float* mask_s     = (float*)(smem + OFF_MASK);
    float* q_s        = (float*)(smem + OFF_QD);
    float* p_s        = (float*)(smem + OFF_PS);

    const int h = blockIdx.x, b = blockIdx.y;
    const int t = threadIdx.x;
    const int lane = t & 31;

    // ---- stage xt[b] (64 KB), mask, fourier weights ----
    {
        const ulonglong2* xb4 = (const ulonglong2*)(xt + (size_t)b * Cn * Ln);
        #pragma unroll
        for (int i = 0; i < 8; i++) xs4[t + i * 512] = xb4[t + i * 512];
    }
    if (t < Cn) mask_s[t] = mask_token[t];
    for (int i = t; i < HC * 24; i += 512) {
        int cc = i / 24, m = i - cc * 24;
        ws[i] = weights[(h * HC + cc) * 24 + m];
    }
    __syncthreads();

    // ---- QKV GEMM: 96 rows x 64 cols, k=256 ----
    {
        const int rg = t >> 4;           // channel within head: 0..31
        const int cg = t & 15;           // col group: cols cg*4..cg*4+3
        const float4* wq = (const float4*)(enc_w + (size_t)(h * HC + rg) * Cn);
        const float4* wk = wq + (Cn * Cn / 4);
        const float4* wv = wk + (Cn * Cn / 4);

        unsigned long long aq0 = 0, aq1 = 0, ak0 = 0, ak1 = 0, av0 = 0, av1 = 0;

        #pragma unroll 4
        for (int j4 = 0; j4 < 64; j4++) {
            const float4 q4 = wq[j4], k4 = wk[j4], v4 = wv[j4];
            const ulonglong2 xv0 = xs4[(j4 * 4 + 0) * 16 + cg];
            const ulonglong2 xv1 = xs4[(j4 * 4 + 1) * 16 + cg];
            const ulonglong2 xv2 = xs4[(j4 * 4 + 2) * 16 + cg];
            const ulonglong2 xv3 = xs4[(j4 * 4 + 3) * 16 + cg];
            unsigned long long d;
            d = dup2(q4.x); fma2(aq0, d, xv0.x); fma2(aq1, d, xv0.y);
            d = dup2(q4.y); fma2(aq0, d, xv1.x); fma2(aq1, d, xv1.y);
            d = dup2(q4.z); fma2(aq0, d, xv2.x); fma2(aq1, d, xv2.y);
            d = dup2(q4.w); fma2(aq0, d, xv3.x); fma2(aq1, d, xv3.y);
            d = dup2(k4.x); fma2(ak0, d, xv0.x); fma2(ak1, d, xv0.y);
            d = dup2(k4.y); fma2(ak0, d, xv1.x); fma2(ak1, d, xv1.y);
            d = dup2(k4.z); fma2(ak0, d, xv2.x); fma2(ak1, d, xv2.y);
            d = dup2(k4.w); fma2(ak0, d, xv3.x); fma2(ak1, d, xv3.y);
            d = dup2(v4.x); fma2(av0, d, xv0.x); fma2(av1, d, xv0.y);
            d = dup2(v4.y); fma2(av0, d, xv1.x); fma2(av1, d, xv1.y);
            d = dup2(v4.z); fma2(av0, d, xv2.x); fma2(av1, d, xv2.y);
            d = dup2(v4.w); fma2(av0, d, xv3.x); fma2(av1, d, xv3.y);
        }

        const float bq = enc_b[h * HC + rg];
        const float bk = enc_b[Cn + h * HC + rg];
        const float bv = enc_b[2 * Cn + h * HC + rg];
        const int s0 = cg * 4;
        float2 p0, p1;
        p0 = unpk(aq0); p1 = unpk(aq1);
        qs[(s0+0)*33+rg] = p0.x + bq; qs[(s0+1)*33+rg] = p0.y + bq;
        qs[(s0+2)*33+rg] = p1.x + bq; qs[(s0+3)*33+rg] = p1.y + bq;
        p0 = unpk(ak0); p1 = unpk(ak1);
        ks[(s0+0)*33+rg] = p0.x + bk; ks[(s0+1)*33+rg] = p0.y + bk;
        ks[(s0+2)*33+rg] = p1.x + bk; ks[(s0+3)*33+rg] = p1.y + bk;
        p0 = unpk(av0); p1 = unpk(av1);
        vs[(s0+0)*33+rg] = p0.x + bv; vs[(s0+1)*33+rg] = p0.y + bv;
        vs[(s0+2)*33+rg] = p1.x + bv; vs[(s0+3)*33+rg] = p1.y + bv;
    }
    __syncthreads();

    // ---- encoder attention ----
    const int l = (t >> 5) * 4 + (lane >> 3);
    const int g = lane & 7;

    float q[HC];
    #pragma unroll
    for (int cc = 0; cc < HC; cc++) q[cc] = qs[l * 33 + cc];

    float dloc[8];
    float mx = -1e30f;
    #pragma unroll
    for (int i = 0; i < 8; i++) {
        const int s = g + i * 8;
        float d = 0.f;
        #pragma unroll
        for (int cc = 0; cc < HC; cc++) d = fmaf(q[cc], ks[s * 33 + cc], d);
        d *= SQRT32;
        dloc[i] = d;
        mx = fmaxf(mx, d);
    }
    mx = fmaxf(mx, __shfl_xor_sync(0xffffffffu, mx, 1));
    mx = fmaxf(mx, __shfl_xor_sync(0xffffffffu, mx, 2));
    mx = fmaxf(mx, __shfl_xor_sync(0xffffffffu, mx, 4));

    float sum = 0.f;
    #pragma unroll
    for (int i = 0; i < 8; i++) {
        const float e = __expf(dloc[i] - mx);
        dloc[i] = e;
        sum += e;
    }
    sum += __shfl_xor_sync(0xffffffffu, sum, 1);
    sum += __shfl_xor_sync(0xffffffffu, sum, 2);
    sum += __shfl_xor_sync(0xffffffffu, sum, 4);
    const float inv = 1.f / sum;

    float acc[4];
    #pragma unroll
    for (int j = 0; j < 4; j++) acc[j] = 0.f;
    #pragma unroll 16
    for (int s = 0; s < 64; s++) {
        const int src = (lane & 24) | (s & 7);
        const float p = __shfl_sync(0xffffffffu, dloc[s >> 3], src);
        #pragma unroll
        for (int j = 0; j < 4; j++) acc[j] = fmaf(p, vs[s * 33 + g * 4 + j], acc[j]);
    }

    // ---- fourier + residual (xt residual from the staged smem copy) ----
    const float* xs_f = (const float*)xs4;
    #pragma unroll
    for (int j = 0; j < 4; j++) {
        const int cc = g * 4 + j;
        const float a = acc[j] * inv;
        const float phi = a * (PI_F / (float)Mn);
        float s1, c1;
        __sincosf(phi, &s1, &c1);
        const float* w = ws + cc * 24;
        float fv = w[Mn];
        float sm = s1, cm = c1;
        #pragma unroll
        for (int m = 1; m < Mn; m++) {
            fv = fmaf(w[m], sm, fv);
            fv = fmaf(w[Mn + m], cm, fv);
            float sn = sm * c1 + cm * s1;
            cm = cm * c1 - sm * s1;
            sm = sn;
        }
        es[cc * 65 + l] = fv + xs_f[(h * HC + cc) * Ln + l];
    }

    // ---- decoder q: 16 threads per output row ----
    {
        const int c = t >> 4, part = t & 15;
        const int row = h * HC + c;
        const float4* wp = (const float4*)(dec_w + row * Cn) + part * 4;
        const float4* mp = (const float4*)(mask_s) + part * 4;
        float a4 = 0.f;
        #pragma unroll
        for (int i = 0; i < 4; i++) {
            float4 w4 = wp[i], m4 = mp[i];
            a4 = fmaf(w4.x, m4.x, a4); a4 = fmaf(w4.y, m4.y, a4);
            a4 = fmaf(w4.z, m4.z, a4); a4 = fmaf(w4.w, m4.w, a4);
        }
        a4 += __shfl_xor_sync(0xffffffffu, a4, 1);
        a4 += __shfl_xor_sync(0xffffffffu, a4, 2);
        a4 += __shfl_xor_sync(0xffffffffu, a4, 4);
        a4 += __shfl_xor_sync(0xffffffffu, a4, 8);
        if (part == 0) q_s[c] = a4 + dec_b[row];
    }
    __syncthreads();

    if (t < Ln) {
        float d = 0.f;
        #pragma unroll
        for (int cc = 0; cc < HC; cc++) d = fmaf(q_s[cc], es[cc * 65 + t], d);
        p_s[t] = d * SQRT32;
    }
    __syncthreads();

    if (t < 32) {
        float v0 = p_s[t], v1 = p_s[t + 32];
        float m = fmaxf(v0, v1);
        #pragma unroll
        for (int off2 = 16; off2; off2 >>= 1) m = fmaxf(m, __shfl_xor_sync(0xffffffffu, m, off2));
        float e0 = __expf(v0 - m), e1 = __expf(v1 - m);
        float s = e0 + e1;
        #pragma unroll
        for (int off2 = 16; off2; off2 >>= 1) s += __shfl_xor_sync(0xffffffffu, s, off2);
        float pin = 1.f / s;
        p_s[t]      = e0 * pin;
        p_s[t + 32] = e1 * pin;
    }
    __syncthreads();

    if (t < HC) {
        float a5 = 0.f;
        #pragma unroll
        for (int ll = 0; ll < Ln; ll++) a5 = fmaf(p_s[ll], es[t * 65 + ll], a5);
        g_xncol[b * Cn + h * HC + t] = a5 + mask_s[h * HC + t];
    }
}

// ---------------- kernel 2: broadcast xn + (head MLP + broadcast y) ----------------
__global__ void __launch_bounds__(256) k_bcast(float4* __restrict__ out4,
                                               const float* __restrict__ fc1_w,
                                               const float* __restrict__ fc1_g,
                                               const float* __restrict__ fc1_b,
                                               const float* __restrict__ fc2_w,
                                               const float* __restrict__ fc2_g,
                                               const float* __restrict__ fc2_b)
{
    const int t = threadIdx.x;
    if (blockIdx.x < 2048) {
        const int row = blockIdx.x * 2 + (t >> 7);      // b*Cn + c
        const int lane = t & 127;
        const float v = g_xncol[row];
        const float4 v4 = make_float4(v, v, v, v);
        float4* p = out4 + (size_t)row * 2048 + lane;
        #pragma unroll
        for (int i = 0; i < 16; i++) p[i * 128] = v4;
    } else {
        __shared__ float xn_s[Cn];
        __shared__ float y1_s[Cn];
        __shared__ float y2_s[3];
        const int b = blockIdx.x - 2048;

        xn_s[t] = g_xncol[b * Cn + t];
        __syncthreads();

        {
            float acc = 0.f;
            const float4* wr = (const float4*)(fc1_w + t * Cn);
            const float4* xr = (const float4*)xn_s;
            #pragma unroll 8
            for (int i = 0; i < 64; i++) {
                float4 w4 = wr[i], x4 = xr[i];
                acc = fmaf(w4.x, x4.x, acc); acc = fmaf(w4.y, x4.y, acc);
                acc = fmaf(w4.z, x4.z, acc); acc = fmaf(w4.w, x4.w, acc);
            }
            float y = fc1_g[t] * acc * RS_BN + fc1_b[t];
            y1_s[t] = (y >= 0.f) ? y : 0.2f * y;
        }
        __syncthreads();

        {
            const int w = t >> 5, lane = t & 31;
            if (w < 3) {
                const float4* wr = (const float4*)(fc2_w + w * Cn) + lane * 2;
                const float4* yr = (const float4*)y1_s + lane * 2;
                float acc = 0.f;
                #pragma unroll
                for (int i = 0; i < 2; i++) {
                    float4 w4 = wr[i], y4 = yr[i];
                    acc = fmaf(w4.x, y4.x, acc); acc = fmaf(w4.y, y4.y, acc);
                    acc = fmaf(w4.z, y4.z, acc); acc = fmaf(w4.w, y4.w, acc);
                }
                #pragma unroll
                for (int off = 16; off; off >>= 1) acc += __shfl_xor_sync(0xffffffffu, acc, off);
                if (lane == 0) {
                    float y = fc2_g[w] * acc * RS_BN + fc2_b[w];
                    y2_s[w] = (y >= 0.f) ? y : 0.2f * y;
                }
            }
        }
        __syncthreads();

        const float y0 = y2_s[0], y1 = y2_s[1], y2v = y2_s[2];
        float4 var[3];
        var[0] = make_float4(y0, y1, y2v, y0);
        var[1] = make_float4(y1, y2v, y0, y1);
        var[2] = make_float4(y2v, y0, y1, y2v);
        float4* p = out4 + (size_t)(Bn * Cn * Nn) / 4 + (size_t)b * 6144;
        for (int i = t; i < 6144; i += 256) p[i] = var[i % 3];
    }
}

// ---------------- launch ----------------
extern "C" void kernel_launch(void* const* d_in, const int* in_sizes, int n_in,
                              void* d_out, int out_size)
{
    const float* xt        = (const float*)d_in[0];
    /* xn = d_in[1] never read: fully-masked path */
    const float* weights   = (const float*)d_in[2];
    const float* mask_tok  = (const float*)d_in[3];
    const float* enc_w     = (const float*)d_in[4];
    const float* enc_b     = (const float*)d_in[5];
    const float* dec_w     = (const float*)d_in[6];
    const float* dec_b     = (const float*)d_in[7];
    const float* fc1_w     = (const float*)d_in[8];
    const float* fc1_g     = (const float*)d_in[9];
    const float* fc1_b     = (const float*)d_in[10];
    const float* fc2_w     = (const float*)d_in[11];
    const float* fc2_g     = (const float*)d_in[12];
    const float* fc2_b     = (const float*)d_in[13];
    float* out = (float*)d_out;

    // idempotent; enqueues nothing (capture-safe)
    cudaFuncSetAttribute(k_fused, cudaFuncAttributeMaxDynamicSharedMemorySize, SMEM_TOTAL);

    k_fused<<<dim3(Hn, Bn), 512, SMEM_TOTAL>>>(xt, enc_w, enc_b, weights,
                                               mask_tok, dec_w, dec_b);
    k_bcast<<<2064, 256>>>((float4*)out, fc1_w, fc1_g, fc1_b, fc2_w, fc2_g, fc2_b);
}